// round 4
// baseline (speedup 1.0000x reference)
#include <cuda_runtime.h>

#define B_N 16
#define K_N 20
#define H_N 256
#define W_N 256
#define HW_N 65536
#define RAD 4
#define STRIP_H 64
#define PADH 72      // STRIP_H + 2*RAD (divisible by 9)
#define NSTRIP 4
#define NPART (B_N*NSTRIP)   // 64 partials per class
#define KG 2                 // k's per stats block
#define CH 16                // HW chunks in stats

__device__ float g_stats4[B_N * K_N * CH * 4];
__device__ float g_num[K_N * NPART];
__device__ float g_den[K_N * NPART];

// ---------------------------------------------------------------------------
// Kernel 1: per-(b,k) partial sums over an HW chunk:
//   sum(labels), sum(labels*x_c) c=0..2.  KG k's per block to amortize x loads.
// ---------------------------------------------------------------------------
__global__ __launch_bounds__(256) void stats_kernel(const float* __restrict__ labels,
                                                    const float* __restrict__ inputs) {
    const int kt = blockIdx.x, b = blockIdx.y, ch = blockIdx.z, t = threadIdx.x;
    const int chunk = HW_N / CH;       // 4096 floats
    const int nf4 = chunk / 4;         // 1024 float4

    const float4* X0 = (const float4*)(inputs + (size_t)(b * 3 + 0) * HW_N + ch * chunk);
    const float4* X1 = (const float4*)(inputs + (size_t)(b * 3 + 1) * HW_N + ch * chunk);
    const float4* X2 = (const float4*)(inputs + (size_t)(b * 3 + 2) * HW_N + ch * chunk);
    const float4* L[KG];
    #pragma unroll
    for (int kk = 0; kk < KG; kk++)
        L[kk] = (const float4*)(labels + (size_t)(b * K_N + kt * KG + kk) * HW_N + ch * chunk);

    float acc[KG][4];
    #pragma unroll
    for (int kk = 0; kk < KG; kk++)
        #pragma unroll
        for (int j = 0; j < 4; j++) acc[kk][j] = 0.f;

    #pragma unroll 4
    for (int i = t; i < nf4; i += 256) {
        const float4 x0 = X0[i], x1 = X1[i], x2 = X2[i];
        #pragma unroll
        for (int kk = 0; kk < KG; kk++) {
            const float4 l = L[kk][i];
            acc[kk][0] += (l.x + l.y) + (l.z + l.w);
            acc[kk][1] = fmaf(l.x, x0.x, fmaf(l.y, x0.y, fmaf(l.z, x0.z, fmaf(l.w, x0.w, acc[kk][1]))));
            acc[kk][2] = fmaf(l.x, x1.x, fmaf(l.y, x1.y, fmaf(l.z, x1.z, fmaf(l.w, x1.w, acc[kk][2]))));
            acc[kk][3] = fmaf(l.x, x2.x, fmaf(l.y, x2.y, fmaf(l.z, x2.z, fmaf(l.w, x2.w, acc[kk][3]))));
        }
    }

    #pragma unroll
    for (int kk = 0; kk < KG; kk++)
        #pragma unroll
        for (int j = 0; j < 4; j++)
            #pragma unroll
            for (int o = 16; o; o >>= 1)
                acc[kk][j] += __shfl_down_sync(0xffffffffu, acc[kk][j], o);

    __shared__ float red[8][KG * 4];
    const int wid = t >> 5, lane = t & 31;
    if (lane == 0) {
        #pragma unroll
        for (int kk = 0; kk < KG; kk++)
            #pragma unroll
            for (int j = 0; j < 4; j++) red[wid][kk * 4 + j] = acc[kk][j];
    }
    __syncthreads();
    if (t < KG * 4) {
        float v = 0.f;
        #pragma unroll
        for (int w = 0; w < 8; w++) v += red[w][t];
        const int k = kt * KG + (t >> 2);
        g_stats4[((b * K_N + k) * CH + ch) * 4 + (t & 3)] = v;
    }
}

// ---------------------------------------------------------------------------
// Kernel 2: adjoint-fused main pass, barrier-free, 4 columns/thread.
//   num_k = sum (l*w) * blur(l),  den_k = sum w * blur(l)
// h-blur: 3 aligned float4 loads per thread per row (12-value window).
// v-blur: 9-deep register rings (blurred + raw labels), static indices.
// Block = 64 threads = one (b,k,strip); thread owns 4 output columns.
// ---------------------------------------------------------------------------
__global__ __launch_bounds__(64) void main_kernel(const float* __restrict__ labels,
                                                  const float* __restrict__ inputs) {
    const int t = threadIdx.x;
    const int s = blockIdx.x;   // strip 0..3
    const int k = blockIdx.y;
    const int b = blockIdx.z;

    // g(d) = exp(-d^2 / (2*5^2)) -> literal immediates (FFMA-imm, rt=1)
    constexpr float G[9] = {0.72614903f, 0.83527021f, 0.92311635f, 0.98019867f, 1.0f,
                            0.98019867f, 0.92311635f, 0.83527021f, 0.72614903f};

    __shared__ float sstat[4];
    if (t < 4) {
        float v = 0.f;
        #pragma unroll
        for (int ch = 0; ch < CH; ch++)
            v += g_stats4[((b * K_N + k) * CH + ch) * 4 + t];
        sstat[t] = v;
    }
    __syncthreads();
    // class_mean_c = sumX_c / (sumL + 1e-5*HW)
    const float inv = 1.0f / (sstat[0] + 0.65536f);
    const float cm0 = sstat[1] * inv, cm1 = sstat[2] * inv, cm2 = sstat[3] * inv;

    const float* lab = labels + (size_t)(b * K_N + k) * HW_N;
    const float* xp0 = inputs + (size_t)(b * 3) * HW_N;
    const float* xp1 = xp0 + HW_N;
    const float* xp2 = xp1 + HW_N;

    const int row0 = s * STRIP_H - RAD;   // global row of padded row 0
    const int oc0 = 4 * t;                // first of this thread's 4 columns

    const bool vldL = (t > 0);            // cols oc0-4..oc0-1 in range
    const bool vldR = (t < 63);           // cols oc0+4..oc0+7 in range

    float rb0[9], rb1[9], rb2[9], rb3[9]; // ring: h-blurred labels
    float ra0[9], ra1[9], ra2[9], ra3[9]; // ring: raw center labels
    float numAcc = 0.f, denAcc = 0.f;

    for (int prb = 0; prb < PADH; prb += 9) {
        #pragma unroll
        for (int u = 0; u < 9; u++) {
            const int pr = prb + u;
            const int gr = row0 + pr;
            const bool rowOK = ((unsigned)gr < (unsigned)H_N);
            const float* rp = lab + gr * W_N + oc0;

            // --- 12-value horizontal window via 3 aligned float4 LDG ---
            float v[12];
            {
                float4 a = make_float4(0.f, 0.f, 0.f, 0.f);
                float4 c = a, d = a;
                if (rowOK) {
                    if (vldL) a = __ldg((const float4*)(rp - 4));
                    c = __ldg((const float4*)rp);
                    if (vldR) d = __ldg((const float4*)(rp + 4));
                }
                v[0] = a.x; v[1] = a.y; v[2]  = a.z; v[3]  = a.w;
                v[4] = c.x; v[5] = c.y; v[6]  = c.z; v[7]  = c.w;
                v[8] = d.x; v[9] = d.y; v[10] = d.z; v[11] = d.w;
            }

            // --- horizontal 9-tap for 4 columns ---
            float h0 = v[0] * G[0], h1 = v[1] * G[0], h2 = v[2] * G[0], h3 = v[3] * G[0];
            #pragma unroll
            for (int j = 1; j < 9; j++) {
                h0 = fmaf(v[j],     G[j], h0);
                h1 = fmaf(v[j + 1], G[j], h1);
                h2 = fmaf(v[j + 2], G[j], h2);
                h3 = fmaf(v[j + 3], G[j], h3);
            }
            rb0[u] = h0; rb1[u] = h1; rb2[u] = h2; rb3[u] = h3;   // slot pr%9 == u
            ra0[u] = v[4]; ra1[u] = v[5]; ra2[u] = v[6]; ra3[u] = v[7];

            // --- vertical 9-tap completes output row gor = s*64 + pr - 8 ---
            if (pr >= 8) {
                float B0 = 0.f, B1 = 0.f, B2 = 0.f, B3 = 0.f;
                #pragma unroll
                for (int j = 0; j < 9; j++) {
                    const int slot = (u + 1 + j) % 9;   // (pr-8+j)%9, static
                    B0 = fmaf(rb0[slot], G[j], B0);
                    B1 = fmaf(rb1[slot], G[j], B1);
                    B2 = fmaf(rb2[slot], G[j], B2);
                    B3 = fmaf(rb3[slot], G[j], B3);
                }
                const int cs = (u + 5) % 9;             // slot of center row (pr-4)
                const float l0 = ra0[cs], l1 = ra1[cs], l2 = ra2[cs], l3 = ra3[cs];

                const int gor = s * STRIP_H + pr - 8;
                const int idx = gor * W_N + oc0;
                const float4 x0 = __ldg((const float4*)(xp0 + idx));
                const float4 x1 = __ldg((const float4*)(xp1 + idx));
                const float4 x2 = __ldg((const float4*)(xp2 + idx));

                float w[4];
                {
                    const float a0 = x0.x - cm0, a1 = x1.x - cm1, a2 = x2.x - cm2;
                    const float dd = fmaf(a0, a0, fmaf(a1, a1, a2 * a2));
                    w[0] = __expf(-dd * dd);
                }
                {
                    const float a0 = x0.y - cm0, a1 = x1.y - cm1, a2 = x2.y - cm2;
                    const float dd = fmaf(a0, a0, fmaf(a1, a1, a2 * a2));
                    w[1] = __expf(-dd * dd);
                }
                {
                    const float a0 = x0.z - cm0, a1 = x1.z - cm1, a2 = x2.z - cm2;
                    const float dd = fmaf(a0, a0, fmaf(a1, a1, a2 * a2));
                    w[2] = __expf(-dd * dd);
                }
                {
                    const float a0 = x0.w - cm0, a1 = x1.w - cm1, a2 = x2.w - cm2;
                    const float dd = fmaf(a0, a0, fmaf(a1, a1, a2 * a2));
                    w[3] = __expf(-dd * dd);
                }

                numAcc = fmaf(l0 * w[0], B0, numAcc);
                numAcc = fmaf(l1 * w[1], B1, numAcc);
                numAcc = fmaf(l2 * w[2], B2, numAcc);
                numAcc = fmaf(l3 * w[3], B3, numAcc);
                denAcc = fmaf(w[0], B0, denAcc);
                denAcc = fmaf(w[1], B1, denAcc);
                denAcc = fmaf(w[2], B2, denAcc);
                denAcc = fmaf(w[3], B3, denAcc);
            }
        }
    }

    // --- deterministic block reduction (2 warps) ---
    #pragma unroll
    for (int o = 16; o; o >>= 1) {
        numAcc += __shfl_down_sync(0xffffffffu, numAcc, o);
        denAcc += __shfl_down_sync(0xffffffffu, denAcc, o);
    }
    __shared__ float rn[2], rd[2];
    if ((t & 31) == 0) { rn[t >> 5] = numAcc; rd[t >> 5] = denAcc; }
    __syncthreads();
    if (t == 0) {
        const float n = rn[0] + rn[1];
        const float d = rd[0] + rd[1];
        const int idx = (k * B_N + b) * NSTRIP + s;
        g_num[idx] = n;
        g_den[idx] = d;
    }
}

// ---------------------------------------------------------------------------
// Kernel 3: final deterministic reduction -> scalar loss
// ---------------------------------------------------------------------------
__global__ void finish_kernel(float* __restrict__ out) {
    __shared__ float sv[K_N];
    const int t = threadIdx.x;
    if (t < K_N) {
        float n = 0.f, d = 0.f;
        for (int i = 0; i < NPART; i++) {
            n += g_num[t * NPART + i];
            d += g_den[t * NPART + i];
        }
        sv[t] = fabsf(n / (d + 1e-6f));
    }
    __syncthreads();
    if (t == 0) {
        float loss = 0.f;
        for (int i = 0; i < K_N; i++) loss += sv[i];
        out[0] = (float)K_N - loss;
    }
}

// ---------------------------------------------------------------------------
extern "C" void kernel_launch(void* const* d_in, const int* in_sizes, int n_in,
                              void* d_out, int out_size) {
    (void)n_in; (void)out_size;
    const float* labels;
    const float* inputs;
    if (in_sizes[0] == B_N * K_N * HW_N) {
        labels = (const float*)d_in[0];
        inputs = (const float*)d_in[1];
    } else {
        labels = (const float*)d_in[1];
        inputs = (const float*)d_in[0];
    }
    float* out = (float*)d_out;

    stats_kernel<<<dim3(K_N / KG, B_N, CH), 256>>>(labels, inputs);
    main_kernel<<<dim3(NSTRIP, K_N, B_N), 64>>>(labels, inputs);
    finish_kernel<<<1, 32>>>(out);
}